// round 6
// baseline (speedup 1.0000x reference)
#include <cuda_runtime.h>
#include <math.h>

#define NN 6000
#define EE 120000
#define DD 128
#define DE 128
#define HH 4
#define LL 2
#define CC 384      // 2*DD + DE
#define HD 512      // HH*DD
#define D4 512      // 4*DD

#define ASTR 132    // smem tile row stride (floats)
#define BSTR 136    // smem B chunk row stride (floats)

// ---------------- scratch (device globals; no allocation) ----------------
__device__ float    g_nupd[(size_t)EE * DD];
__device__ float    g_eattr[(size_t)EE * DE];
__device__ float    g_scores[(size_t)EE * HH];
__device__ float    g_att[(size_t)EE * HH];
__device__ unsigned g_smaxu[NN * HH];
__device__ float    g_norm[NN * HH];
__device__ float    g_agg[(size_t)NN * HD];
__device__ float    g_nodes[NN * DD];
__device__ float    g_upd[NN * DD];
__device__ float    g_dense[(size_t)NN * D4];
__device__ float    g_dense2[NN * DD];
__device__ float    g_Wa[(size_t)LL * CC * HD];    // attention W packed [l][c][h*D+d]
__device__ float    g_WU1[(size_t)LL * DD * 1280]; // [Wa_src|Wa_snk|nW1_src|nW1_snk]
__device__ float    g_WU2[(size_t)LL * DD * 256];  // [eW1_src|eW1_snk]
__device__ float    g_U1[(size_t)NN * 1280];       // per-node partials (attn + nmlp1)
__device__ float    g_U2[(size_t)NN * 256];        // per-node partials (emlp1)
__device__ float    g_zero[1536];                  // zero bias (never written)

// ---------------- helpers ----------------
__device__ __forceinline__ float gelu_f(float x) {
    return 0.5f * x * (1.0f + erff(x * 0.70710678118654752440f));
}
__device__ __forceinline__ unsigned f2u(float f) {
    unsigned u = __float_as_uint(f);
    return (u & 0x80000000u) ? ~u : (u | 0x80000000u);
}
__device__ __forceinline__ float u2f(unsigned u) {
    return (u & 0x80000000u) ? __uint_as_float(u & 0x7fffffffu) : __uint_as_float(~u);
}
__device__ __forceinline__ float tf32f(float x) {
    unsigned r;
    asm("cvt.rna.tf32.f32 %0, %1;" : "=r"(r) : "f"(x));
    return __uint_as_float(r);
}
__device__ __forceinline__ float4 tf32f4(float4 v) {
    return make_float4(tf32f(v.x), tf32f(v.y), tf32f(v.z), tf32f(v.w));
}
__device__ __forceinline__ void mma_tf32(float* d, const unsigned* a, const unsigned* b) {
    asm volatile(
        "mma.sync.aligned.m16n8k8.row.col.f32.tf32.tf32.f32 "
        "{%0,%1,%2,%3}, {%4,%5,%6,%7}, {%8,%9}, {%0,%1,%2,%3};"
        : "+f"(d[0]), "+f"(d[1]), "+f"(d[2]), "+f"(d[3])
        : "r"(a[0]), "r"(a[1]), "r"(a[2]), "r"(a[3]), "r"(b[0]), "r"(b[1]));
}

// ---------------- small kernels ----------------
__global__ void pack_wa(const float* __restrict__ aW) {
    int i = blockIdx.x * blockDim.x + threadIdx.x;
    if (i >= LL * HH * CC * DD) return;
    int d = i % DD;
    int c = (i / DD) % CC;
    int h = (i / (DD * CC)) % HH;
    int l = i / (DD * CC * HH);
    g_Wa[((size_t)l * CC + c) * HD + h * DD + d] = aW[i];
}

__global__ void pack_u1(const float* __restrict__ aW, const float* __restrict__ nW1) {
    int i = blockIdx.x * blockDim.x + threadIdx.x;
    if (i >= LL * DD * 1280) return;
    int j = i % 1280;
    int k = (i / 1280) % DD;
    int l = i / (1280 * DD);
    float v;
    if (j < 1024) {
        int c = (j < 512) ? k : (128 + k);
        int jj = j & 511;
        int h = jj >> 7, d = jj & 127;
        v = aW[(((size_t)l * HH + h) * CC + c) * DD + d];
    } else {
        int c = (j < 1152) ? k : (128 + k);
        int d = (j - 1024) & 127;
        v = nW1[((size_t)l * CC + c) * DD + d];
    }
    g_WU1[i] = v;
}

__global__ void pack_u2(const float* __restrict__ eW1) {
    int i = blockIdx.x * blockDim.x + threadIdx.x;
    if (i >= LL * DD * 256) return;
    int j = i % 256;
    int k = (i / 256) % DD;
    int l = i / (256 * DD);
    int c = (j < 128) ? k : (128 + k);
    g_WU2[i] = eW1[((size_t)l * CC + c) * DE + (j & 127)];
}

__global__ void node_embed(const int* __restrict__ seq, const float* __restrict__ emb) {
    int i = blockIdx.x * blockDim.x + threadIdx.x;
    if (i < NN * DD) g_nodes[i] = emb[seq[i / DD] * DD + (i % DD)];
}

__global__ void edge_init(const float* __restrict__ dist,
                          const float* __restrict__ W, const float* __restrict__ b) {
    int e = blockIdx.x;
    int t = threadIdx.x;
    __shared__ float rbf[16];
    if (t < 16) {
        float mu = 2.0f + (20.0f / 15.0f) * (float)t;
        float z = (dist[e] - mu) * (1.0f / 1.25f);
        rbf[t] = expf(-z * z) + 1e-8f;
    }
    __syncthreads();
    float acc = b[t];
#pragma unroll
    for (int k = 0; k < 16; k++) acc = fmaf(rbf[k], W[k * DE + t], acc);
    g_eattr[(size_t)e * DE + t] = acc;
}

__global__ void smax_init() {
    int i = blockIdx.x * blockDim.x + threadIdx.x;
    if (i < NN * HH) { g_smaxu[i] = 0u; g_norm[i] = 0.0f; }
}

__global__ void smax_atomic(const int* __restrict__ snk) {
    int i = blockIdx.x * blockDim.x + threadIdx.x;
    if (i >= EE * HH) return;
    int e = i / HH, h = i % HH;
    atomicMax(&g_smaxu[snk[e] * HH + h], f2u(g_scores[i]));
}

__global__ void att_kernel(const int* __restrict__ snk) {
    int i = blockIdx.x * blockDim.x + threadIdx.x;
    if (i >= EE * HH) return;
    int e = i / HH, h = i % HH;
    int s = snk[e];
    float a = expf(g_scores[i] - u2f(g_smaxu[s * HH + h]));
    g_att[i] = a;
    atomicAdd(&g_norm[s * HH + h], a + 1e-12f);
}

__global__ void recip_norm() {
    int i = blockIdx.x * blockDim.x + threadIdx.x;
    if (i < NN * HH) g_norm[i] = 1.0f / g_norm[i];
}

__global__ void zero_agg() {
    int i = blockIdx.x * blockDim.x + threadIdx.x;
    if (i < NN * HD) g_agg[i] = 0.0f;
}

__global__ void aggregate(const int* __restrict__ snk) {
    int i = blockIdx.x * blockDim.x + threadIdx.x;
    if (i >= EE * 32) return;
    int e = i >> 5;
    int d4 = i & 31;
    float4 v = ((const float4*)g_nupd)[(size_t)e * 32 + d4];
    int s = snk[e];
    float4 w = *(const float4*)(g_att + e * 4);
    float4 rn = *(const float4*)(g_norm + s * 4);
    float4* base = (float4*)(g_agg + (size_t)s * HD) + d4;
    float c0 = w.x * rn.x, c1 = w.y * rn.y, c2 = w.z * rn.z, c3 = w.w * rn.w;
    atomicAdd(base,      make_float4(c0 * v.x, c0 * v.y, c0 * v.z, c0 * v.w));
    atomicAdd(base + 32, make_float4(c1 * v.x, c1 * v.y, c1 * v.z, c1 * v.w));
    atomicAdd(base + 64, make_float4(c2 * v.x, c2 * v.y, c2 * v.z, c2 * v.w));
    atomicAdd(base + 96, make_float4(c3 * v.x, c3 * v.y, c3 * v.z, c3 * v.w));
}

__global__ void ln_kernel(const float* __restrict__ A, const float* __restrict__ R,
                          const float* __restrict__ g, const float* __restrict__ b,
                          float* __restrict__ out, float* __restrict__ out2) {
    int r = blockIdx.x;
    int t = threadIdx.x;
    float x = A[(size_t)r * DD + t] + R[(size_t)r * DD + t];
    float s = x;
#pragma unroll
    for (int o = 16; o > 0; o >>= 1) s += __shfl_xor_sync(0xffffffffu, s, o);
    __shared__ float ws[4], ws2[4];
    if ((t & 31) == 0) ws[t >> 5] = s;
    __syncthreads();
    float mean = (ws[0] + ws[1] + ws[2] + ws[3]) * (1.0f / DD);
    float dx = x - mean;
    float v = dx * dx;
#pragma unroll
    for (int o = 16; o > 0; o >>= 1) v += __shfl_xor_sync(0xffffffffu, v, o);
    if ((t & 31) == 0) ws2[t >> 5] = v;
    __syncthreads();
    float var = (ws2[0] + ws2[1] + ws2[2] + ws2[3]) * (1.0f / DD);
    float res = dx * (1.0f / sqrtf(var + 1e-5f)) * g[t] + b[t];
    out[(size_t)r * DD + t] = res;
    if (out2) out2[(size_t)r * DD + t] = res;
}

// ---------------- smem-resident GEMM core (K=128) ----------------
// acc = As(tile,[128][ASTR],tf32) @ B(global [128][ldb], 128 cols), warp tile 64x32.
__device__ __forceinline__ void gemm_sm(
    const float* __restrict__ As, const float* __restrict__ B, int ldb,
    float* __restrict__ Bs, float acc[4][4][4],
    int tid, int wm0, int wn0, int g, int tig) {
#pragma unroll
    for (int mt = 0; mt < 4; mt++)
#pragma unroll
        for (int nt = 0; nt < 4; nt++)
#pragma unroll
            for (int q = 0; q < 4; q++) acc[mt][nt][q] = 0.0f;
    const int brow = tid >> 5, bcol = (tid & 31) * 4;
    const float* Bp = B + (size_t)brow * ldb + bcol;
    float4 br0 = *(const float4*)Bp;
    float4 br1 = *(const float4*)(Bp + (size_t)8 * ldb);
    *(float4*)&Bs[brow * BSTR + bcol] = tf32f4(br0);
    *(float4*)&Bs[(brow + 8) * BSTR + bcol] = tf32f4(br1);
    __syncthreads();
    int buf = 0;
#pragma unroll 1
    for (int k0 = 0; k0 < 128; k0 += 16, buf ^= 1) {
        const bool more = k0 < 112;
        if (more) {
            br0 = *(const float4*)(Bp + (size_t)(k0 + 16) * ldb);
            br1 = *(const float4*)(Bp + (size_t)(k0 + 24) * ldb);
        }
        const float* Bb = Bs + buf * 16 * BSTR;
#pragma unroll
        for (int ks = 0; ks < 16; ks += 8) {
            unsigned af[4][4], bf[4][2];
#pragma unroll
            for (int mt = 0; mt < 4; mt++) {
                const float* ar = As + (wm0 + mt * 16 + g) * ASTR + k0 + ks + tig;
                af[mt][0] = __float_as_uint(ar[0]);
                af[mt][1] = __float_as_uint(ar[8 * ASTR]);
                af[mt][2] = __float_as_uint(ar[4]);
                af[mt][3] = __float_as_uint(ar[8 * ASTR + 4]);
            }
#pragma unroll
            for (int nt = 0; nt < 4; nt++) {
                const float* br = Bb + (ks + tig) * BSTR + wn0 + nt * 8 + g;
                bf[nt][0] = __float_as_uint(br[0]);
                bf[nt][1] = __float_as_uint(br[4 * BSTR]);
            }
#pragma unroll
            for (int mt = 0; mt < 4; mt++)
#pragma unroll
                for (int nt = 0; nt < 4; nt++)
                    mma_tf32(acc[mt][nt], af[mt], bf[nt]);
        }
        if (more) {
            float* Bd = Bs + (buf ^ 1) * 16 * BSTR;
            *(float4*)&Bd[brow * BSTR + bcol] = tf32f4(br0);
            *(float4*)&Bd[(brow + 8) * BSTR + bcol] = tf32f4(br1);
        }
        __syncthreads();
    }
}

__device__ __forceinline__ void load_tile(float* buf, const float* __restrict__ Gp,
                                          int e0, int M, int tid) {
#pragma unroll
    for (int i = 0; i < 16; i++) {
        int idx = tid + i * 256;
        int r = idx >> 5, c = (idx & 31) * 4;
        int gr = min(e0 + r, M - 1);
        *(float4*)&buf[r * ASTR + c] = tf32f4(*(const float4*)(Gp + (size_t)gr * DE + c));
    }
}

// ---------------- mega1: attention scores + node-update MLP chain ----------------
__global__ void __launch_bounds__(256, 1) mega1_kernel(
    const float* __restrict__ eattr,
    const float* __restrict__ Wae, const float* __restrict__ aWb,
    const float* __restrict__ aA, const float* __restrict__ aAb,
    const float* __restrict__ nW1e, const float* __restrict__ nb1,
    const float* __restrict__ nW2, const float* __restrict__ nb2,
    const float* __restrict__ nW3, const float* __restrict__ nb3,
    const int* __restrict__ srcI, const int* __restrict__ snkI) {
    extern __shared__ float sm[];
    float* bufE = sm;
    float* buf1 = sm + 16896;
    float* buf2 = sm + 33792;
    float* Bs   = sm + 50688;
    float* sred = sm + 55040;
    const int tid = threadIdx.x;
    const int e0 = blockIdx.x * 128;
    const int wid = tid >> 5, lane = tid & 31, g = lane >> 2, tig = lane & 3;
    const int wm0 = (wid >> 2) * 64, wn0 = (wid & 3) * 32, wn = wid & 3;
    float acc[4][4][4];

    load_tile(bufE, eattr, e0, EE, tid);
    __syncthreads();

    int sIr[4][2], kIr[4][2];
#pragma unroll
    for (int mt = 0; mt < 4; mt++)
#pragma unroll
        for (int i2 = 0; i2 < 2; i2++) {
            int gr = min(e0 + wm0 + mt * 16 + i2 * 8 + g, EE - 1);
            sIr[mt][i2] = srcI[gr];
            kIr[mt][i2] = snkI[gr];
        }

    // ---- attention: 4 head GEMMs, scores written directly ----
#pragma unroll 1
    for (int h = 0; h < HH; h++) {
        gemm_sm(bufE, Wae + h * 128, HD, Bs, acc, tid, wm0, wn0, g, tig);
#pragma unroll
        for (int mt = 0; mt < 4; mt++)
#pragma unroll
            for (int i2 = 0; i2 < 2; i2++) {
                int rl = wm0 + mt * 16 + i2 * 8 + g;
                float p = 0.0f;
#pragma unroll
                for (int nt = 0; nt < 4; nt++) {
                    int c = wn0 + nt * 8 + 2 * tig;
                    int gc = h * 128 + c;
                    float2 bb = *(const float2*)&aWb[gc];
                    float2 us = *(const float2*)&g_U1[(size_t)sIr[mt][i2] * 1280 + gc];
                    float2 uk = *(const float2*)&g_U1[(size_t)kIr[mt][i2] * 1280 + 512 + gc];
                    float v0 = acc[mt][nt][i2 * 2 + 0] + bb.x + us.x + uk.x;
                    float v1 = acc[mt][nt][i2 * 2 + 1] + bb.y + us.y + uk.y;
                    v0 = (v0 > 0.0f) ? v0 : 0.2f * v0;
                    v1 = (v1 > 0.0f) ? v1 : 0.2f * v1;
                    float2 a2 = *(const float2*)&aA[gc];
                    p = fmaf(v0, a2.x, p);
                    p = fmaf(v1, a2.y, p);
                }
                p += __shfl_xor_sync(0xffffffffu, p, 1);
                p += __shfl_xor_sync(0xffffffffu, p, 2);
                if (tig == 0) sred[rl * 5 + wn] = p;
            }
        __syncthreads();
        if (tid < 128) {
            int gr = e0 + tid;
            if (gr < EE)
                g_scores[gr * HH + h] = sred[tid * 5 + 0] + sred[tid * 5 + 1] +
                                        sred[tid * 5 + 2] + sred[tid * 5 + 3] + aAb[h];
        }
    }

    // ---- nmlp1: + U1 gathers, gelu -> buf1 ----
    gemm_sm(bufE, nW1e, DD, Bs, acc, tid, wm0, wn0, g, tig);
#pragma unroll
    for (int mt = 0; mt < 4; mt++)
#pragma unroll
        for (int i2 = 0; i2 < 2; i2++) {
            int rl = wm0 + mt * 16 + i2 * 8 + g;
#pragma unroll
            for (int nt = 0; nt < 4; nt++) {
                int c = wn0 + nt * 8 + 2 * tig;
                float2 bb = *(const float2*)&nb1[c];
                float2 us = *(const float2*)&g_U1[(size_t)sIr[mt][i2] * 1280 + 1024 + c];
                float2 uk = *(const float2*)&g_U1[(size_t)kIr[mt][i2] * 1280 + 1152 + c];
                buf1[rl * ASTR + c]     = tf32f(gelu_f(acc[mt][nt][i2 * 2 + 0] + bb.x + us.x + uk.x));
                buf1[rl * ASTR + c + 1] = tf32f(gelu_f(acc[mt][nt][i2 * 2 + 1] + bb.y + us.y + uk.y));
            }
        }

    // ---- nmlp2: gelu -> buf2 ----
    gemm_sm(buf1, nW2, DD, Bs, acc, tid, wm0, wn0, g, tig);
#pragma unroll
    for (int mt = 0; mt < 4; mt++)
#pragma unroll
        for (int i2 = 0; i2 < 2; i2++) {
            int rl = wm0 + mt * 16 + i2 * 8 + g;
#pragma unroll
            for (int nt = 0; nt < 4; nt++) {
                int c = wn0 + nt * 8 + 2 * tig;
                float2 bb = *(const float2*)&nb2[c];
                buf2[rl * ASTR + c]     = tf32f(gelu_f(acc[mt][nt][i2 * 2 + 0] + bb.x));
                buf2[rl * ASTR + c + 1] = tf32f(gelu_f(acc[mt][nt][i2 * 2 + 1] + bb.y));
            }
        }

    // ---- nmlp3: -> g_nupd ----
    gemm_sm(buf2, nW3, DD, Bs, acc, tid, wm0, wn0, g, tig);
#pragma unroll
    for (int mt = 0; mt < 4; mt++)
#pragma unroll
        for (int i2 = 0; i2 < 2; i2++) {
            int rl = wm0 + mt * 16 + i2 * 8 + g;
            int gr = e0 + rl;
            if (gr >= EE) continue;
#pragma unroll
            for (int nt = 0; nt < 4; nt++) {
                int c = wn0 + nt * 8 + 2 * tig;
                float2 bb = *(const float2*)&nb3[c];
                *(float2*)&g_nupd[(size_t)gr * DD + c] =
                    make_float2(acc[mt][nt][i2 * 2 + 0] + bb.x, acc[mt][nt][i2 * 2 + 1] + bb.y);
            }
        }
}

// ---------------- mega2: edge MLP chain + fused residual LayerNorm ----------------
__global__ void __launch_bounds__(256, 1) mega2_kernel(
    const float* __restrict__ eattr,
    const float* __restrict__ eW1e, const float* __restrict__ eb1,
    const float* __restrict__ eW2, const float* __restrict__ eb2,
    const float* __restrict__ eW3, const float* __restrict__ eb3,
    const int* __restrict__ srcI, const int* __restrict__ snkI,
    const float* __restrict__ egv, const float* __restrict__ ebv,
    float* __restrict__ eout, float* __restrict__ oout) {
    extern __shared__ float sm[];
    float* bufE = sm;
    float* buf1 = sm + 16896;
    float* buf2 = sm + 33792;
    float* Bs   = sm + 50688;
    const int tid = threadIdx.x;
    const int e0 = blockIdx.x * 128;
    const int wid = tid >> 5, lane = tid & 31, g = lane >> 2, tig = lane & 3;
    const int wm0 = (wid >> 2) * 64, wn0 = (wid & 3) * 32;
    float acc[4][4][4];

    load_tile(bufE, eattr, e0, EE, tid);
    __syncthreads();

    int sIr[4][2], kIr[4][2];
#pragma unroll
    for (int mt = 0; mt < 4; mt++)
#pragma unroll
        for (int i2 = 0; i2 < 2; i2++) {
            int gr = min(e0 + wm0 + mt * 16 + i2 * 8 + g, EE - 1);
            sIr[mt][i2] = srcI[gr];
            kIr[mt][i2] = snkI[gr];
        }

    // ---- emlp1: + U2 gathers, gelu -> buf1 ----
    gemm_sm(bufE, eW1e, DE, Bs, acc, tid, wm0, wn0, g, tig);
#pragma unroll
    for (int mt = 0; mt < 4; mt++)
#pragma unroll
        for (int i2 = 0; i2 < 2; i2++) {
            int rl = wm0 + mt * 16 + i2 * 8 + g;
#pragma unroll
            for (int nt = 0; nt < 4; nt++) {
                int c = wn0 + nt * 8 + 2 * tig;
                float2 bb = *(const float2*)&eb1[c];
                float2 us = *(const float2*)&g_U2[(size_t)sIr[mt][i2] * 256 + c];
                float2 uk = *(const float2*)&g_U2[(size_t)kIr[mt][i2] * 256 + 128 + c];
                buf1[rl * ASTR + c]     = tf32f(gelu_f(acc[mt][nt][i2 * 2 + 0] + bb.x + us.x + uk.x));
                buf1[rl * ASTR + c + 1] = tf32f(gelu_f(acc[mt][nt][i2 * 2 + 1] + bb.y + us.y + uk.y));
            }
        }

    // ---- emlp2: gelu -> buf2 ----
    gemm_sm(buf1, eW2, DE, Bs, acc, tid, wm0, wn0, g, tig);
#pragma unroll
    for (int mt = 0; mt < 4; mt++)
#pragma unroll
        for (int i2 = 0; i2 < 2; i2++) {
            int rl = wm0 + mt * 16 + i2 * 8 + g;
#pragma unroll
            for (int nt = 0; nt < 4; nt++) {
                int c = wn0 + nt * 8 + 2 * tig;
                float2 bb = *(const float2*)&eb2[c];
                buf2[rl * ASTR + c]     = tf32f(gelu_f(acc[mt][nt][i2 * 2 + 0] + bb.x));
                buf2[rl * ASTR + c + 1] = tf32f(gelu_f(acc[mt][nt][i2 * 2 + 1] + bb.y));
            }
        }

    // ---- emlp3: eu -> buf1 (full precision) ----
    gemm_sm(buf2, eW3, DE, Bs, acc, tid, wm0, wn0, g, tig);
#pragma unroll
    for (int mt = 0; mt < 4; mt++)
#pragma unroll
        for (int i2 = 0; i2 < 2; i2++) {
            int rl = wm0 + mt * 16 + i2 * 8 + g;
#pragma unroll
            for (int nt = 0; nt < 4; nt++) {
                int c = wn0 + nt * 8 + 2 * tig;
                float2 bb = *(const float2*)&eb3[c];
                buf1[rl * ASTR + c]     = acc[mt][nt][i2 * 2 + 0] + bb.x;
                buf1[rl * ASTR + c + 1] = acc[mt][nt][i2 * 2 + 1] + bb.y;
            }
        }
    __syncthreads();

    // ---- fused residual LayerNorm: out = LN(eattr + eu) * g + b ----
    {
        int r = tid >> 1, hh = tid & 1;
        int gr = e0 + r;
        int grc = min(gr, EE - 1);
        float s = 0.0f, sq = 0.0f;
#pragma unroll
        for (int j = 0; j < 16; j++) {
            int c = hh * 64 + j * 4;
            float4 a = *(const float4*)&eattr[(size_t)grc * DE + c];
            float4 u = *(const float4*)&buf1[r * ASTR + c];
            float x0 = a.x + u.x, x1 = a.y + u.y, x2 = a.z + u.z, x3 = a.w + u.w;
            s += x0 + x1 + x2 + x3;
            sq += x0 * x0 + x1 * x1 + x2 * x2 + x3 * x3;
            *(float4*)&buf2[r * ASTR + c] = make_float4(x0, x1, x2, x3);
        }
        s  += __shfl_xor_sync(0xffffffffu, s, 1);
        sq += __shfl_xor_sync(0xffffffffu, sq, 1);
        float mean = s * (1.0f / 128.0f);
        float var = sq * (1.0f / 128.0f) - mean * mean;
        float rstd = rsqrtf(var + 1e-5f);
        if (gr < EE) {
#pragma unroll
            for (int j = 0; j < 16; j++) {
                int c = hh * 64 + j * 4;
                float4 x = *(const float4*)&buf2[r * ASTR + c];
                float4 gv = *(const float4*)&egv[c];
                float4 bv = *(const float4*)&ebv[c];
                float4 o;
                o.x = (x.x - mean) * rstd * gv.x + bv.x;
                o.y = (x.y - mean) * rstd * gv.y + bv.y;
                o.z = (x.z - mean) * rstd * gv.z + bv.z;
                o.w = (x.w - mean) * rstd * gv.w + bv.w;
                *(float4*)&eout[(size_t)gr * DE + c] = o;
                if (oout) *(float4*)&oout[(size_t)gr * DE + c] = o;
            }
        }
    }
}

// ---------------- generic tf32 GEMM (node-side, from R5) ----------------
template <int ACT>
__global__ void __launch_bounds__(256) gemm_tc(
    const float* __restrict__ A, int lda,
    const float* __restrict__ B, int ldb,
    const float* __restrict__ bias,
    float* __restrict__ C, int ldc, int M, int K) {
    __shared__ float As[2][128][20];
    __shared__ float Bsm[2][16][136];
    const int tid = threadIdx.x;
    const int row0 = blockIdx.y * 128, col0 = blockIdx.x * 128;
    const int wid = tid >> 5, lane = tid & 31, g = lane >> 2, tig = lane & 3;
    const int wm0 = (wid >> 2) * 64, wn0 = (wid & 3) * 32;

    const int arow = tid >> 2, acol = (tid & 3) * 4;
    const int ag0 = min(row0 + arow, M - 1);
    const int ag1 = min(row0 + arow + 64, M - 1);
    const int brow = tid >> 5, bcol = (tid & 31) * 4;

    const float* Ap0 = A + (size_t)ag0 * lda + acol;
    const float* Ap1 = A + (size_t)ag1 * lda + acol;
    const float* Bp  = B + (size_t)brow * ldb + col0 + bcol;

    float4 ar0 = *(const float4*)Ap0;
    float4 ar1 = *(const float4*)Ap1;
    float4 br0 = *(const float4*)Bp;
    float4 br1 = *(const float4*)(Bp + (size_t)8 * ldb);
    *(float4*)&As[0][arow][acol]      = tf32f4(ar0);
    *(float4*)&As[0][arow + 64][acol] = tf32f4(ar1);
    *(float4*)&Bsm[0][brow][bcol]     = tf32f4(br0);
    *(float4*)&Bsm[0][brow + 8][bcol] = tf32f4(br1);
    __syncthreads();

    float acc[4][4][4] = {};
    int buf = 0;
    for (int k0 = 0; k0 < K; k0 += 16, buf ^= 1) {
        const bool more = (k0 + 16) < K;
        if (more) {
            ar0 = *(const float4*)(Ap0 + k0 + 16);
            ar1 = *(const float4*)(Ap1 + k0 + 16);
            br0 = *(const float4*)(Bp + (size_t)(k0 + 16) * ldb);
            br1 = *(const float4*)(Bp + (size_t)(k0 + 24) * ldb);
        }
#pragma unroll
        for (int ks = 0; ks < 16; ks += 8) {
            unsigned af[4][4], bf[4][2];
#pragma unroll
            for (int mt = 0; mt < 4; mt++) {
                int r = wm0 + mt * 16 + g;
                af[mt][0] = __float_as_uint(As[buf][r][ks + tig]);
                af[mt][1] = __float_as_uint(As[buf][r + 8][ks + tig]);
                af[mt][2] = __float_as_uint(As[buf][r][ks + tig + 4]);
                af[mt][3] = __float_as_uint(As[buf][r + 8][ks + tig + 4]);
            }
#pragma unroll
            for (int nt = 0; nt < 4; nt++) {
                int c = wn0 + nt * 8 + g;
                bf[nt][0] = __float_as_uint(Bsm[buf][ks + tig][c]);
                bf[nt][1] = __float_as_uint(Bsm[buf][ks + tig + 4][c]);
            }
#pragma unroll
            for (int mt = 0; mt < 4; mt++)
#pragma unroll
                for (int nt = 0; nt < 4; nt++)
                    mma_tf32(acc[mt][nt], af[mt], bf[nt]);
        }
        if (more) {
            *(float4*)&As[buf ^ 1][arow][acol]      = tf32f4(ar0);
            *(float4*)&As[buf ^ 1][arow + 64][acol] = tf32f4(ar1);
            *(float4*)&Bsm[buf ^ 1][brow][bcol]     = tf32f4(br0);
            *(float4*)&Bsm[buf ^ 1][brow + 8][bcol] = tf32f4(br1);
        }
        __syncthreads();
    }

#pragma unroll
    for (int mt = 0; mt < 4; mt++) {
#pragma unroll
        for (int i2 = 0; i2 < 2; i2++) {
            int gr = row0 + wm0 + mt * 16 + i2 * 8 + g;
            if (gr >= M) continue;
#pragma unroll
            for (int nt = 0; nt < 4; nt++) {
                int gc = col0 + wn0 + nt * 8 + 2 * tig;
                float2 bb = *(const float2*)&bias[gc];
                float v0 = acc[mt][nt][i2 * 2 + 0] + bb.x;
                float v1 = acc[mt][nt][i2 * 2 + 1] + bb.y;
                if (ACT == 1) { v0 = gelu_f(v0); v1 = gelu_f(v1); }
                *(float2*)&C[(size_t)gr * ldc + gc] = make_float2(v0, v1);
            }
        }
    }
}

// ---------------- host ----------------
static inline void* sym(const void* s) {
    void* p = nullptr;
    cudaGetSymbolAddress(&p, s);
    return p;
}

extern "C" void kernel_launch(void* const* d_in, const int* in_sizes, int n_in,
                              void* d_out, int out_size) {
    const int*   seq      = (const int*)d_in[0];
    const int*   eidx     = (const int*)d_in[1];
    const float* dist     = (const float*)d_in[2];
    const float* seq_emb  = (const float*)d_in[3];
    const float* elW      = (const float*)d_in[4];
    const float* elb      = (const float*)d_in[5];
    const float* aW_W     = (const float*)d_in[6];
    const float* aW_b     = (const float*)d_in[7];
    const float* aA_W     = (const float*)d_in[8];
    const float* aA_b     = (const float*)d_in[9];
    const float* nW1 = (const float*)d_in[10]; const float* nb1 = (const float*)d_in[11];
    const float* nW2 = (const float*)d_in[12]; const float* nb2 = (const float*)d_in[13];
    const float* nW3 = (const float*)d_in[14]; const float* nb3 = (const float*)d_in[15];
    const float* dW1 = (const float*)d_in[16]; const float* db1 = (const float*)d_in[17];
    const float* dW2 = (const float*)d_in[18]; const float* db2 = (const float*)d_in[19];
    const float* eW1 = (const float*)d_in[20]; const float* eb1 = (const float*)d_in[21];
    const float* eW2 = (const float*)d_in[22]; const float* eb2 = (const float*)d_in[23];
    const float* eW3 = (const float*)d_in[24]; const float* eb3 = (const float*)d_in[25];
    const float* agW = (const float*)d_in[26]; const float* agb = (const float*)d_in[27];
    const float* n1g = (const float*)d_in[28]; const float* n1b = (const float*)d_in[29];
    const float* eg  = (const float*)d_in[30]; const float* eb  = (const float*)d_in[31];

    const int* srcp = eidx;
    const int* snkp = eidx + EE;

    float* agg    = (float*)sym(g_agg);
    float* nodes  = (float*)sym(g_nodes);
    float* upd    = (float*)sym(g_upd);
    float* dense  = (float*)sym(g_dense);
    float* dense2 = (float*)sym(g_dense2);
    float* Wa     = (float*)sym(g_Wa);
    float* WU1    = (float*)sym(g_WU1);
    float* WU2    = (float*)sym(g_WU2);
    float* U1     = (float*)sym(g_U1);
    float* U2     = (float*)sym(g_U2);
    float* zerob  = (float*)sym(g_zero);
    float* eattr  = (float*)sym(g_eattr);

    const int SM1 = 55680 * 4;   // mega1 dynamic smem bytes
    const int SM2 = 55040 * 4;   // mega2 dynamic smem bytes
    cudaFuncSetAttribute(mega1_kernel, cudaFuncAttributeMaxDynamicSharedMemorySize, SM1);
    cudaFuncSetAttribute(mega2_kernel, cudaFuncAttributeMaxDynamicSharedMemorySize, SM2);

    const int EB  = (EE + 127) / 128;  // 938
    const int GMN = (NN + 127) / 128;

    {
        pack_wa<<<(LL * HH * CC * DD + 255) / 256, 256>>>(aW_W);
        pack_u1<<<(LL * DD * 1280 + 255) / 256, 256>>>(aW_W, nW1);
        pack_u2<<<(LL * DD * 256 + 255) / 256, 256>>>(eW1);
        node_embed<<<(NN * DD + 255) / 256, 256>>>(seq, seq_emb);
        edge_init<<<EE, 128>>>(dist, elW, elb);
    }

    for (int l = 0; l < LL; l++) {
        const bool last = (l == LL - 1);

        // per-node partials for attn + nmlp1
        gemm_tc<0><<<dim3(10, GMN), 256>>>(nodes, DD, WU1 + (size_t)l * DD * 1280, 1280,
                                           zerob, U1, 1280, NN, DD);

        // fused attention scores + node-update MLP chain
        mega1_kernel<<<EB, 256, SM1>>>(
            eattr, Wa + ((size_t)l * CC + 256) * HD, aW_b + l * HD,
            aA_W + l * HD, aA_b + l * HH,
            nW1 + ((size_t)l * CC + 256) * DD, nb1 + l * DD,
            nW2 + (size_t)l * DD * DD, nb2 + l * DD,
            nW3 + (size_t)l * DD * DD, nb3 + l * DD,
            srcp, snkp);

        // scatter softmax over sink nodes
        smax_init<<<(NN * HH + 255) / 256, 256>>>();
        smax_atomic<<<(EE * HH + 255) / 256, 256>>>(snkp);
        att_kernel<<<(EE * HH + 255) / 256, 256>>>(snkp);
        recip_norm<<<(NN * HH + 255) / 256, 256>>>();

        // aggregation
        zero_agg<<<(NN * HD + 255) / 256, 256>>>();
        aggregate<<<(EE * 32 + 255) / 256, 256>>>(snkp);

        // node update + LN + dense MLP + LN
        gemm_tc<0><<<dim3(1, GMN), 256>>>(agg, HD, agW + (size_t)l * HD * DD, DD,
                                          agb + l * DD, upd, DD, NN, HD);
        ln_kernel<<<NN, 128>>>(nodes, upd, n1g + l * DD, n1b + l * DD, nodes, nullptr);
        gemm_tc<1><<<dim3(4, GMN), 256>>>(nodes, DD, dW1 + (size_t)l * DD * D4, D4,
                                          db1 + l * D4, dense, D4, NN, DD);
        gemm_tc<0><<<dim3(1, GMN), 256>>>(dense, D4, dW2 + (size_t)l * D4 * DD, DD,
                                          db2 + l * DD, dense2, DD, NN, D4);
        ln_kernel<<<NN, 128>>>(dense2, upd, n1g + l * DD, n1b + l * DD, nodes,
                               last ? (float*)d_out : nullptr);

        // per-node partials for emlp1 (new nodes)
        gemm_tc<0><<<dim3(2, GMN), 256>>>(nodes, DD, WU2 + (size_t)l * DD * 256, 256,
                                          zerob, U2, 256, NN, DD);

        // fused edge MLP chain + residual LayerNorm
        mega2_kernel<<<EB, 256, SM2>>>(
            eattr,
            eW1 + ((size_t)l * CC + 256) * DE, eb1 + l * DE,
            eW2 + (size_t)l * DE * DE, eb2 + l * DE,
            eW3 + (size_t)l * DE * DE, eb3 + l * DE,
            srcp, snkp, eg + l * DE, eb + l * DE,
            eattr, last ? ((float*)d_out + (size_t)NN * DD) : nullptr);
    }
}